// round 2
// baseline (speedup 1.0000x reference)
#include <cuda_runtime.h>

#define N_NODES 100000
#define N_EDGES 1600000
#define IN_F    64
#define HID     128
#define N_CLS   10

#define FINAL_BLOCKS ((N_NODES + 255) / 256)   // 391

// ---------------- device scratch (no allocations allowed) ----------------
__device__ int   g_deg[N_NODES];            // in-degree histogram (no self-loop)
__device__ int   g_ptr[N_NODES + 1];        // CSR offsets
__device__ int   g_cur[N_NODES];            // fill cursors
__device__ float g_dis[N_NODES];            // deg^{-1/2} (incl. self-loop)
__device__ int   g_srcs[N_EDGES];           // CSR: source node per in-edge
__device__ float g_aggx[(size_t)N_NODES * IN_F];   // \hat{A} x   (25.6 MB)
__device__ float g_z[(size_t)N_NODES * N_CLS];     // relu(...)W2 (4 MB)
__device__ float g_part[FINAL_BLOCKS * 11];        // block partials (10 sums + lse)

// ---------------- K1: zero degree histogram ----------------
__global__ void k_init() {
    int i = blockIdx.x * blockDim.x + threadIdx.x;
    if (i < N_NODES) g_deg[i] = 0;
}

// ---------------- K2: degree histogram over col (edge_index is int32!) -------
__global__ void k_hist(const int* __restrict__ ei) {
    int i = blockIdx.x * blockDim.x + threadIdx.x;   // exactly N_EDGES threads
    int c = ei[N_EDGES + i];                         // col = edge_index[1]
    if ((unsigned)c < (unsigned)N_NODES)             // guard: turns bad dtype into wrong-answer, not crash
        atomicAdd(&g_deg[c], 1);
}

// ---------------- K3: single-block exclusive scan + rsqrt norms ----------------
__global__ void k_scan() {
    __shared__ int wsum[32];
    __shared__ int s_carry;
    const int tid = threadIdx.x, lane = tid & 31, wid = tid >> 5;
    if (tid == 0) s_carry = 0;
    __syncthreads();
    for (int base = 0; base < N_NODES; base += 1024) {
        int i = base + tid;
        int v = (i < N_NODES) ? g_deg[i] : 0;
        int x = v;
        #pragma unroll
        for (int o = 1; o < 32; o <<= 1) {
            int t = __shfl_up_sync(0xffffffffu, x, o);
            if (lane >= o) x += t;
        }
        if (lane == 31) wsum[wid] = x;
        __syncthreads();
        if (wid == 0) {
            int t = wsum[lane];
            #pragma unroll
            for (int o = 1; o < 32; o <<= 1) {
                int u = __shfl_up_sync(0xffffffffu, t, o);
                if (lane >= o) t += u;
            }
            wsum[lane] = t;
        }
        __syncthreads();
        int incl  = x + (wid > 0 ? wsum[wid - 1] : 0);
        int carry = s_carry;
        int excl  = carry + incl - v;
        if (i < N_NODES) {
            g_ptr[i] = excl;
            g_cur[i] = excl;
            g_dis[i] = rsqrtf((float)(v + 1));   // +1 self-loop
        }
        __syncthreads();
        if (tid == 1023) s_carry = carry + incl;
        __syncthreads();
    }
    if (tid == 0) g_ptr[N_NODES] = s_carry;
}

// ---------------- K4: CSR fill ----------------
__global__ void k_csrfill(const int* __restrict__ ei) {
    int i = blockIdx.x * blockDim.x + threadIdx.x;   // exactly N_EDGES threads
    int r = ei[i];
    int c = ei[N_EDGES + i];
    if ((unsigned)c < (unsigned)N_NODES && (unsigned)r < (unsigned)N_NODES) {
        int pos = atomicAdd(&g_cur[c], 1);
        g_srcs[pos] = r;
    }
}

// ---------------- K5: agg = \hat{A} x  (warp per node, 64 feat via float2) ------
__global__ void k_aggx(const float* __restrict__ x) {
    int warp = (blockIdx.x * blockDim.x + threadIdx.x) >> 5;
    int lane = threadIdx.x & 31;
    if (warp >= N_NODES) return;
    const float2* __restrict__ x2 = (const float2*)x;
    float di = g_dis[warp];
    float2 v = x2[(size_t)warp * 32 + lane];
    float w0 = di * di;
    float2 acc;
    acc.x = w0 * v.x;
    acc.y = w0 * v.y;
    int p = g_ptr[warp], e = g_ptr[warp + 1];
    // unroll-by-4 for MLP
    for (; p + 4 <= e; p += 4) {
        int r0 = g_srcs[p], r1 = g_srcs[p + 1], r2 = g_srcs[p + 2], r3 = g_srcs[p + 3];
        float a0 = g_dis[r0] * di, a1 = g_dis[r1] * di, a2 = g_dis[r2] * di, a3 = g_dis[r3] * di;
        float2 u0 = x2[(size_t)r0 * 32 + lane];
        float2 u1 = x2[(size_t)r1 * 32 + lane];
        float2 u2 = x2[(size_t)r2 * 32 + lane];
        float2 u3 = x2[(size_t)r3 * 32 + lane];
        acc.x += a0 * u0.x; acc.y += a0 * u0.y;
        acc.x += a1 * u1.x; acc.y += a1 * u1.y;
        acc.x += a2 * u2.x; acc.y += a2 * u2.y;
        acc.x += a3 * u3.x; acc.y += a3 * u3.y;
    }
    for (; p < e; ++p) {
        int r = g_srcs[p];
        float w = g_dis[r] * di;
        float2 u = x2[(size_t)r * 32 + lane];
        acc.x += w * u.x; acc.y += w * u.y;
    }
    ((float2*)g_aggx)[(size_t)warp * 32 + lane] = acc;
}

// ---------------- K6: fused z = relu(agg @ W1 + b1) @ W2  --------------------
// Block: 256 threads = 8 warps. Tile: 64 rows x 128 cols (full N of W1).
// Thread (ty,tx): rows ty*8..+7, cols tx*4..+3. Then GEMM2 via butterfly reduce.
__global__ void __launch_bounds__(256, 2) k_fused_gemm(
    const float* __restrict__ W1, const float* __restrict__ b1,
    const float* __restrict__ W2)
{
    __shared__ __align__(16) float sW1[IN_F * HID];     // 32 KB
    __shared__ __align__(16) float sW2[HID * N_CLS];    // 5 KB
    __shared__ float sA[64 * 33];                       // 8.4 KB (padded)

    const int tid = threadIdx.x;
    const int tx = tid & 31, ty = tid >> 5;
    const int row0 = blockIdx.x * 64;

    for (int t = tid; t < IN_F * HID; t += 256) sW1[t] = W1[t];
    for (int t = tid; t < HID * N_CLS; t += 256) sW2[t] = W2[t];

    float acc[8][4];
    #pragma unroll
    for (int m = 0; m < 8; m++)
        #pragma unroll
        for (int j = 0; j < 4; j++) acc[m][j] = 0.f;

    for (int kb = 0; kb < IN_F; kb += 32) {
        __syncthreads();
        // stage A chunk: 64 rows x 32 k, coalesced global, conflict-free smem
        for (int t = tid; t < 64 * 32; t += 256) {
            int m = t >> 5, kk = t & 31;
            int gr = row0 + m;
            float v = (gr < N_NODES) ? g_aggx[(size_t)gr * IN_F + kb + kk] : 0.f;
            sA[m * 33 + kk] = v;
        }
        __syncthreads();
        #pragma unroll
        for (int kk = 0; kk < 32; kk++) {
            float4 b = *(const float4*)&sW1[(kb + kk) * HID + tx * 4];
            #pragma unroll
            for (int m = 0; m < 8; m++) {
                float a = sA[(ty * 8 + m) * 33 + kk];   // broadcast
                acc[m][0] += a * b.x;
                acc[m][1] += a * b.y;
                acc[m][2] += a * b.z;
                acc[m][3] += a * b.w;
            }
        }
    }

    // epilogue: +b1, relu, GEMM2 (k split across lanes), butterfly reduce
    float4 b1v = *(const float4*)&b1[tx * 4];
    float w2r[40];
    #pragma unroll
    for (int j = 0; j < 4; j++)
        #pragma unroll
        for (int c = 0; c < N_CLS; c++)
            w2r[j * 10 + c] = sW2[(tx * 4 + j) * N_CLS + c];

    #pragma unroll
    for (int m = 0; m < 8; m++) {
        float h0 = fmaxf(acc[m][0] + b1v.x, 0.f);
        float h1 = fmaxf(acc[m][1] + b1v.y, 0.f);
        float h2 = fmaxf(acc[m][2] + b1v.z, 0.f);
        float h3 = fmaxf(acc[m][3] + b1v.w, 0.f);
        float p[10];
        #pragma unroll
        for (int c = 0; c < N_CLS; c++)
            p[c] = h0 * w2r[c] + h1 * w2r[10 + c] + h2 * w2r[20 + c] + h3 * w2r[30 + c];
        #pragma unroll
        for (int off = 16; off > 0; off >>= 1)
            #pragma unroll
            for (int c = 0; c < N_CLS; c++)
                p[c] += __shfl_xor_sync(0xffffffffu, p[c], off);
        int gr = row0 + ty * 8 + m;
        if (gr < N_NODES && tx < N_CLS)
            g_z[(size_t)gr * N_CLS + tx] = p[tx];
    }
}

// ---------------- K7: agg z (10-dim), +b2, log_softmax, block partials -------
__global__ void k_final(const float* __restrict__ b2) {
    const int tid = threadIdx.x, lane = tid & 31, wid = tid >> 5;
    int i = blockIdx.x * blockDim.x + tid;
    float vals[11];
    #pragma unroll
    for (int v = 0; v < 11; v++) vals[v] = 0.f;

    if (i < N_NODES) {
        const float2* __restrict__ z2 = (const float2*)g_z;
        float di = g_dis[i];
        float w0 = di * di;
        float a[10];
        #pragma unroll
        for (int q = 0; q < 5; q++) {
            float2 u = z2[(size_t)i * 5 + q];
            a[2 * q] = w0 * u.x;
            a[2 * q + 1] = w0 * u.y;
        }
        int p = g_ptr[i], e = g_ptr[i + 1];
        for (; p + 2 <= e; p += 2) {
            int r0 = g_srcs[p], r1 = g_srcs[p + 1];
            float wA = g_dis[r0] * di, wB = g_dis[r1] * di;
            #pragma unroll
            for (int q = 0; q < 5; q++) {
                float2 uA = z2[(size_t)r0 * 5 + q];
                float2 uB = z2[(size_t)r1 * 5 + q];
                a[2 * q]     += wA * uA.x + wB * uB.x;
                a[2 * q + 1] += wA * uA.y + wB * uB.y;
            }
        }
        for (; p < e; ++p) {
            int r = g_srcs[p];
            float w = g_dis[r] * di;
            #pragma unroll
            for (int q = 0; q < 5; q++) {
                float2 u = z2[(size_t)r * 5 + q];
                a[2 * q]     += w * u.x;
                a[2 * q + 1] += w * u.y;
            }
        }
        float mx = -1e30f;
        #pragma unroll
        for (int c = 0; c < 10; c++) { a[c] += b2[c]; mx = fmaxf(mx, a[c]); }
        float se = 0.f;
        #pragma unroll
        for (int c = 0; c < 10; c++) se += expf(a[c] - mx);
        float lse = mx + logf(se);
        #pragma unroll
        for (int c = 0; c < 10; c++) vals[c] = a[c];
        vals[10] = lse;
    }

    // warp reduce, then cross-warp via smem + warp0
    #pragma unroll
    for (int v = 0; v < 11; v++)
        #pragma unroll
        for (int off = 16; off > 0; off >>= 1)
            vals[v] += __shfl_xor_sync(0xffffffffu, vals[v], off);

    __shared__ float sw[8][11];
    if (lane == 0)
        #pragma unroll
        for (int v = 0; v < 11; v++) sw[wid][v] = vals[v];
    __syncthreads();
    if (wid == 0) {
        #pragma unroll
        for (int v = 0; v < 11; v++) {
            float t = (lane < 8) ? sw[lane][v] : 0.f;
            #pragma unroll
            for (int off = 4; off > 0; off >>= 1)
                t += __shfl_xor_sync(0xffffffffu, t, off);
            if (lane == 0) g_part[blockIdx.x * 11 + v] = t;
        }
    }
}

// ---------------- K8: final reduce over block partials -> d_out --------------
__global__ void k_reduce(float* __restrict__ out) {
    const int tid = threadIdx.x, lane = tid & 31, wid = tid >> 5;
    float s[11];
    #pragma unroll
    for (int v = 0; v < 11; v++) {
        float t = 0.f;
        for (int b = tid; b < FINAL_BLOCKS; b += 256) t += g_part[b * 11 + v];
        s[v] = t;
    }
    #pragma unroll
    for (int v = 0; v < 11; v++)
        #pragma unroll
        for (int off = 16; off > 0; off >>= 1)
            s[v] += __shfl_xor_sync(0xffffffffu, s[v], off);

    __shared__ float sw[8][11];
    __shared__ float tot[11];
    if (lane == 0)
        #pragma unroll
        for (int v = 0; v < 11; v++) sw[wid][v] = s[v];
    __syncthreads();
    if (wid == 0) {
        #pragma unroll
        for (int v = 0; v < 11; v++) {
            float t = (lane < 8) ? sw[lane][v] : 0.f;
            #pragma unroll
            for (int off = 4; off > 0; off >>= 1)
                t += __shfl_xor_sync(0xffffffffu, t, off);
            if (lane == 0) tot[v] = t;
        }
    }
    __syncthreads();
    if (tid < 10) out[tid] = (tot[tid] - tot[10]) * (1.0f / (float)N_NODES);
}

// ---------------- launch ----------------
extern "C" void kernel_launch(void* const* d_in, const int* in_sizes, int n_in,
                              void* d_out, int out_size) {
    const float* x  = (const float*)d_in[0];
    const int*   ei = (const int*)d_in[1];     // edge_index: int32 (JAX x64 disabled)
    const float* W1 = (const float*)d_in[2];
    const float* b1 = (const float*)d_in[3];
    const float* W2 = (const float*)d_in[4];
    const float* b2 = (const float*)d_in[5];
    float* out = (float*)d_out;

    k_init<<<(N_NODES + 255) / 256, 256>>>();
    k_hist<<<N_EDGES / 256, 256>>>(ei);
    k_scan<<<1, 1024>>>();
    k_csrfill<<<N_EDGES / 256, 256>>>(ei);
    k_aggx<<<(N_NODES * 32 + 255) / 256, 256>>>(x);
    k_fused_gemm<<<(N_NODES + 63) / 64, 256>>>(W1, b1, W2);
    k_final<<<FINAL_BLOCKS, 256>>>(b2);
    k_reduce<<<1, 256>>>(out);
}